// round 3
// baseline (speedup 1.0000x reference)
#include <cuda_runtime.h>
#include <math.h>

#define B_ 16
#define C_ 64
#define H_ 192
#define W_ 192
#define R_ 64

// ---------------- scratch (device globals; no allocation) ----------------
__device__ float g_cp[B_ * C_];            // [B][C]
__device__ float g_hp[B_ * H_];            // [B][H]
__device__ float g_wp[B_ * W_];            // [B][W]
__device__ float g_RS[B_ * C_ * H_];       // per-plane row sums  [B][C][H]
__device__ float g_CS[B_ * C_ * W_];       // per-plane col sums  [B][C][W]
__device__ float g_T [B_ * R_ * C_];       // p[r]*sigmoid(Cw)    [B][R][C]
__device__ float g_Hw[B_ * H_ * R_];       // sigmoid(Hw)         [B][H][R]
__device__ float g_Ww[B_ * R_ * W_];       // sigmoid(Ww)         [B][R][W]

// ---------------- f32x2 helpers (Blackwell packed fp32) -------------------
__device__ __forceinline__ unsigned long long pk2(float x, float y) {
    unsigned long long r;
    asm("mov.b64 %0, {%1, %2};" : "=l"(r) : "f"(x), "f"(y));
    return r;
}
__device__ __forceinline__ void fma2(unsigned long long& d,
                                     unsigned long long a,
                                     unsigned long long b) {
    asm("fma.rn.f32x2 %0, %1, %2, %3;" : "=l"(d) : "l"(a), "l"(b), "l"(d));
}
__device__ __forceinline__ float2 upk2(unsigned long long v) {
    float2 f;
    asm("mov.b64 {%0, %1}, %2;" : "=f"(f.x), "=f"(f.y) : "l"(v));
    return f;
}

__device__ __forceinline__ float sigmoidf_(float x) {
    return 1.0f / (1.0f + expf(-x));
}

// ---------------- kernel 1: per-plane pools ------------------------------
// One block per (b,c). 192 threads = 6 warps; warp j owns rows [32j, 32j+32).
// Lane l reads columns l, l+32, ..., l+160. Deterministic (no atomics).
__global__ void __launch_bounds__(192) pool_kernel(const float* __restrict__ X) {
    const int c = blockIdx.x;
    const int b = blockIdx.y;
    const float* plane = X + ((b * C_ + c) * H_) * (long)W_;

    const int tid  = threadIdx.x;
    const int warp = tid >> 5;
    const int lane = tid & 31;

    __shared__ float scs[6][W_];
    __shared__ float swt[6];

    float col0 = 0.f, col1 = 0.f, col2 = 0.f, col3 = 0.f, col4 = 0.f, col5 = 0.f;
    float tot = 0.f;

    const int h0 = warp * 32;
    for (int i = 0; i < 32; i++) {
        const int h = h0 + i;
        const float* row = plane + h * W_;
        float v0 = row[lane +   0];
        float v1 = row[lane +  32];
        float v2 = row[lane +  64];
        float v3 = row[lane +  96];
        float v4 = row[lane + 128];
        float v5 = row[lane + 160];
        col0 += v0; col1 += v1; col2 += v2; col3 += v3; col4 += v4; col5 += v5;
        float rs = ((v0 + v1) + (v2 + v3)) + (v4 + v5);
        #pragma unroll
        for (int off = 16; off >= 1; off >>= 1)
            rs += __shfl_down_sync(0xffffffffu, rs, off);
        if (lane == 0) {
            g_RS[(b * C_ + c) * H_ + h] = rs;
            tot += rs;
        }
    }
    scs[warp][lane +   0] = col0;
    scs[warp][lane +  32] = col1;
    scs[warp][lane +  64] = col2;
    scs[warp][lane +  96] = col3;
    scs[warp][lane + 128] = col4;
    scs[warp][lane + 160] = col5;
    if (lane == 0) swt[warp] = tot;
    __syncthreads();

    float cs = 0.f;
    #pragma unroll
    for (int j = 0; j < 6; j++) cs += scs[j][tid];
    g_CS[(b * C_ + c) * W_ + tid] = cs;

    if (tid == 0) {
        float t = 0.f;
        #pragma unroll
        for (int j = 0; j < 6; j++) t += swt[j];
        g_cp[b * C_ + c] = t * (1.0f / (H_ * (float)W_));
    }
}

// ---------------- kernel 2: reduce RS/CS over c -> hp, wp ----------------
__global__ void hw_pool_kernel() {
    const int i = blockIdx.x * blockDim.x + threadIdx.x;  // 0 .. B*H-1
    if (i >= B_ * H_) return;
    const int b = i / H_;
    const int h = i - b * H_;
    float s1 = 0.f, s2 = 0.f;
    for (int c = 0; c < C_; c++) {
        s1 += g_RS[(b * C_ + c) * H_ + h];
        s2 += g_CS[(b * C_ + c) * W_ + h];
    }
    g_hp[i] = s1 * (1.0f / (C_ * (float)W_));
    g_wp[i] = s2 * (1.0f / (C_ * (float)H_));
}

// ---------------- kernel 3a: T[b][r][c] = p[r]*sigmoid(Wc@cp + bc) -------
__global__ void cw_kernel(const float* __restrict__ Wc,
                          const float* __restrict__ bc,
                          const float* __restrict__ p) {
    const int r = blockIdx.x;
    const int b = blockIdx.y;
    const int d = threadIdx.x;  // 64
    __shared__ float scp[C_];
    scp[d] = g_cp[b * C_ + d];
    __syncthreads();
    const float* wrow = Wc + (r * C_ + d) * C_;
    float acc = bc[r * C_ + d];
    #pragma unroll 8
    for (int c = 0; c < C_; c++) acc += wrow[c] * scp[c];
    g_T[(b * R_ + r) * C_ + d] = p[r] * sigmoidf_(acc);
}

// ---------------- kernel 3b: Hw[b][h][r] = sigmoid(Wh@hp + bh) -----------
// One block per r; each thread d computes all 16 batches (Wh row read once).
__global__ void __launch_bounds__(192) hwgt_kernel(const float* __restrict__ Wh,
                                                   const float* __restrict__ bh) {
    const int r = blockIdx.x;
    const int d = threadIdx.x;  // 0..191
    __shared__ float shp[B_][H_];
    for (int i = d; i < B_ * H_; i += H_) shp[i / H_][i % H_] = g_hp[i];
    __syncthreads();
    const float* wrow = Wh + (r * H_ + d) * H_;
    const float bias = bh[r * H_ + d];
    float acc[B_];
    #pragma unroll
    for (int b = 0; b < B_; b++) acc[b] = bias;
    for (int h = 0; h < H_; h++) {
        const float wv = wrow[h];
        #pragma unroll
        for (int b = 0; b < B_; b++) acc[b] += wv * shp[b][h];
    }
    #pragma unroll
    for (int b = 0; b < B_; b++)
        g_Hw[(b * H_ + d) * R_ + r] = sigmoidf_(acc[b]);
}

// ---------------- kernel 3c: Ww[b][r][w] = sigmoid(Ww@wp + bw) -----------
__global__ void __launch_bounds__(192) wwgt_kernel(const float* __restrict__ Wwp,
                                                   const float* __restrict__ bw) {
    const int r = blockIdx.x;
    const int d = threadIdx.x;
    __shared__ float swp[B_][W_];
    for (int i = d; i < B_ * W_; i += W_) swp[i / W_][i % W_] = g_wp[i];
    __syncthreads();
    const float* wrow = Wwp + (r * W_ + d) * W_;
    const float bias = bw[r * W_ + d];
    float acc[B_];
    #pragma unroll
    for (int b = 0; b < B_; b++) acc[b] = bias;
    for (int w = 0; w < W_; w++) {
        const float wv = wrow[w];
        #pragma unroll
        for (int b = 0; b < B_; b++) acc[b] += wv * swp[b][w];
    }
    #pragma unroll
    for (int b = 0; b < B_; b++)
        g_Ww[(b * R_ + r) * W_ + d] = sigmoidf_(acc[b]);
}

// ---------------- kernel 4: main fused GEMM + elementwise ----------------
// Block = (h, w-half, b). Smem: M[r][c] = T[b][r][c]*Hw[b][h][r] (64x64),
// V[r][w'] = Ww[b][r][half*96 + w'] (64x96). Each of 192 threads owns an
// 8c x 4w register tile computed with packed f32x2 FMAs over r=0..63.
__global__ void __launch_bounds__(192) main_kernel(const float* __restrict__ X,
                                                   float* __restrict__ out) {
    const int h    = blockIdx.x;   // 0..191
    const int half = blockIdx.y;   // 0..1
    const int b    = blockIdx.z;   // 0..15

    const int tid = threadIdx.x;
    const int tc  = tid / 24;      // 0..7
    const int tw  = tid - tc * 24; // 0..23

    __shared__ float sM[R_ * C_];        // 16 KB  [r][c]
    __shared__ float sV[R_ * 96];        // 24 KB  [r][w']
    __shared__ float sh[R_];

    if (tid < R_) sh[tid] = g_Hw[(b * H_ + h) * R_ + tid];
    __syncthreads();

    // fill M = T * hw   (T layout [B][R][C], coalesced float4)
    {
        const float4* T4  = (const float4*)(g_T + b * (R_ * C_));
        float4*       sM4 = (float4*)sM;
        for (int i = tid; i < (R_ * C_) / 4; i += 192) {
            float4 t = T4[i];
            const float hv = sh[i >> 4];  // r = i / (C_/4)
            t.x *= hv; t.y *= hv; t.z *= hv; t.w *= hv;
            sM4[i] = t;
        }
    }
    // fill V half
    {
        float4* sV4 = (float4*)sV;
        for (int i = tid; i < R_ * 24; i += 192) {
            const int r = i / 24;
            const int j = i - r * 24;
            sV4[r * 24 + j] =
                ((const float4*)(g_Ww + (b * R_ + r) * W_ + half * 96))[j];
        }
    }
    __syncthreads();

    const float4* sM4 = (const float4*)sM;
    const float4* sV4 = (const float4*)sV;

    unsigned long long acc[4][4];  // [c-pair][w]
    #pragma unroll
    for (int i = 0; i < 4; i++)
        #pragma unroll
        for (int j = 0; j < 4; j++) acc[i][j] = 0ull;

    #pragma unroll 4
    for (int r = 0; r < R_; r++) {
        const float4 a0 = sM4[r * 16 + tc];       // c = 4tc .. 4tc+3
        const float4 a1 = sM4[r * 16 + 8 + tc];   // c = 32+4tc .. 32+4tc+3
        const float4 bv = sV4[r * 24 + tw];       // w = 4tw .. 4tw+3

        unsigned long long A0 = pk2(a0.x, a0.y);
        unsigned long long A1 = pk2(a0.z, a0.w);
        unsigned long long A2 = pk2(a1.x, a1.y);
        unsigned long long A3 = pk2(a1.z, a1.w);

        unsigned long long Bx = pk2(bv.x, bv.x);
        unsigned long long By = pk2(bv.y, bv.y);
        unsigned long long Bz = pk2(bv.z, bv.z);
        unsigned long long Bw = pk2(bv.w, bv.w);

        fma2(acc[0][0], A0, Bx); fma2(acc[0][1], A0, By);
        fma2(acc[0][2], A0, Bz); fma2(acc[0][3], A0, Bw);
        fma2(acc[1][0], A1, Bx); fma2(acc[1][1], A1, By);
        fma2(acc[1][2], A1, Bz); fma2(acc[1][3], A1, Bw);
        fma2(acc[2][0], A2, Bx); fma2(acc[2][1], A2, By);
        fma2(acc[2][2], A2, Bz); fma2(acc[2][3], A2, Bw);
        fma2(acc[3][0], A3, Bx); fma2(acc[3][1], A3, By);
        fma2(acc[3][2], A3, Bz); fma2(acc[3][3], A3, Bw);
    }

    // unpack: vals[ci][wj], ci: 0..3 -> c = 4tc+ci ; 4..7 -> c = 32+4tc+(ci-4)
    float vals[8][4];
    #pragma unroll
    for (int cp = 0; cp < 4; cp++) {
        #pragma unroll
        for (int wj = 0; wj < 4; wj++) {
            const float2 q = upk2(acc[cp][wj]);
            vals[2 * cp + 0][wj] = q.x;
            vals[2 * cp + 1][wj] = q.y;
        }
    }

    const int w0 = half * 96 + tw * 4;
    #pragma unroll
    for (int ci = 0; ci < 8; ci++) {
        const int c = (ci < 4) ? (tc * 4 + ci) : (32 + tc * 4 + (ci - 4));
        const int idx = ((b * C_ + c) * H_ + h) * W_ + w0;
        const float4 x = *(const float4*)(X + idx);
        float4 o;
        o.x = vals[ci][0] * x.x;
        o.y = vals[ci][1] * x.y;
        o.z = vals[ci][2] * x.z;
        o.w = vals[ci][3] * x.w;
        *(float4*)(out + idx) = o;
    }
}

// ---------------- launch ---------------------------------------------------
extern "C" void kernel_launch(void* const* d_in, const int* in_sizes, int n_in,
                              void* d_out, int out_size) {
    const float* X   = (const float*)d_in[0];
    const float* p   = (const float*)d_in[1];
    const float* Wc  = (const float*)d_in[2];
    const float* bc  = (const float*)d_in[3];
    const float* Wh  = (const float*)d_in[4];
    const float* bh  = (const float*)d_in[5];
    const float* Wwp = (const float*)d_in[6];
    const float* bw  = (const float*)d_in[7];
    float* out = (float*)d_out;

    pool_kernel<<<dim3(C_, B_), 192>>>(X);
    hw_pool_kernel<<<(B_ * H_ + 255) / 256, 256>>>();
    cw_kernel<<<dim3(R_, B_), C_>>>(Wc, bc, p);
    hwgt_kernel<<<R_, H_>>>(Wh, bh);
    wwgt_kernel<<<R_, W_>>>(Wwp, bw);
    main_kernel<<<dim3(H_, 2, B_), 192>>>(X, out);
}

// round 5
// speedup vs baseline: 1.3211x; 1.3211x over previous
#include <cuda_runtime.h>
#include <math.h>

#define B_ 16
#define C_ 64
#define H_ 192
#define W_ 192
#define R_ 64

// ---------------- scratch (device globals; no allocation) ----------------
__device__ float g_cp[B_ * C_];            // [B][C]
__device__ float g_hp[B_ * H_];            // [B][H]
__device__ float g_wp[B_ * W_];            // [B][W]
__device__ float g_RS[B_ * C_ * H_];       // per-plane row sums  [B][C][H]
__device__ float g_CS[B_ * C_ * W_];       // per-plane col sums  [B][C][W]
__device__ float g_T [B_ * R_ * C_];       // p[r]*sigmoid(Cw)    [B][R][C]
__device__ float g_Hw[B_ * H_ * R_];       // sigmoid(Hw)         [B][H][R]
__device__ float g_Ww[B_ * R_ * W_];       // sigmoid(Ww)         [B][R][W]

// ---------------- f32x2 helpers (Blackwell packed fp32) -------------------
__device__ __forceinline__ unsigned long long pk2(float x, float y) {
    unsigned long long r;
    asm("mov.b64 %0, {%1, %2};" : "=l"(r) : "f"(x), "f"(y));
    return r;
}
__device__ __forceinline__ void fma2(unsigned long long& d,
                                     unsigned long long a,
                                     unsigned long long b) {
    asm("fma.rn.f32x2 %0, %1, %2, %3;" : "=l"(d) : "l"(a), "l"(b), "l"(d));
}
__device__ __forceinline__ float2 upk2(unsigned long long v) {
    float2 f;
    asm("mov.b64 {%0, %1}, %2;" : "=f"(f.x), "=f"(f.y) : "l"(v));
    return f;
}

__device__ __forceinline__ float sigmoidf_(float x) {
    return 1.0f / (1.0f + expf(-x));
}

// ---------------- kernel 1: per-plane pools ------------------------------
// One block per (b,c). 192 threads = 6 warps; warp j owns rows [32j, 32j+32).
// Lane l reads columns l, l+32, ..., l+160. Deterministic (no atomics).
__global__ void __launch_bounds__(192) pool_kernel(const float* __restrict__ X) {
    const int c = blockIdx.x;
    const int b = blockIdx.y;
    const float* plane = X + ((b * C_ + c) * H_) * (long)W_;

    const int tid  = threadIdx.x;
    const int warp = tid >> 5;
    const int lane = tid & 31;

    __shared__ float scs[6][W_];
    __shared__ float swt[6];

    float col0 = 0.f, col1 = 0.f, col2 = 0.f, col3 = 0.f, col4 = 0.f, col5 = 0.f;
    float tot = 0.f;

    const int h0 = warp * 32;
    for (int i = 0; i < 32; i++) {
        const int h = h0 + i;
        const float* row = plane + h * W_;
        float v0 = row[lane +   0];
        float v1 = row[lane +  32];
        float v2 = row[lane +  64];
        float v3 = row[lane +  96];
        float v4 = row[lane + 128];
        float v5 = row[lane + 160];
        col0 += v0; col1 += v1; col2 += v2; col3 += v3; col4 += v4; col5 += v5;
        float rs = ((v0 + v1) + (v2 + v3)) + (v4 + v5);
        #pragma unroll
        for (int off = 16; off >= 1; off >>= 1)
            rs += __shfl_down_sync(0xffffffffu, rs, off);
        if (lane == 0) {
            g_RS[(b * C_ + c) * H_ + h] = rs;
            tot += rs;
        }
    }
    scs[warp][lane +   0] = col0;
    scs[warp][lane +  32] = col1;
    scs[warp][lane +  64] = col2;
    scs[warp][lane +  96] = col3;
    scs[warp][lane + 128] = col4;
    scs[warp][lane + 160] = col5;
    if (lane == 0) swt[warp] = tot;
    __syncthreads();

    float cs = 0.f;
    #pragma unroll
    for (int j = 0; j < 6; j++) cs += scs[j][tid];
    g_CS[(b * C_ + c) * W_ + tid] = cs;

    if (tid == 0) {
        float t = 0.f;
        #pragma unroll
        for (int j = 0; j < 6; j++) t += swt[j];
        g_cp[b * C_ + c] = t * (1.0f / (H_ * (float)W_));
    }
}

// ---------------- kernel 2: reduce RS/CS over c -> hp, wp ----------------
__global__ void hw_pool_kernel() {
    const int i = blockIdx.x * blockDim.x + threadIdx.x;  // 0 .. B*H-1
    if (i >= B_ * H_) return;
    const int b = i / H_;
    const int h = i - b * H_;
    float s1 = 0.f, s2 = 0.f;
    for (int c = 0; c < C_; c++) {
        s1 += g_RS[(b * C_ + c) * H_ + h];
        s2 += g_CS[(b * C_ + c) * W_ + h];
    }
    g_hp[i] = s1 * (1.0f / (C_ * (float)W_));
    g_wp[i] = s2 * (1.0f / (C_ * (float)H_));
}

// ---------------- kernel 3: H/W sigmoid weights, warp-per-row GEMV -------
// blockIdx.y: 0 = H branch (Wh,bh -> g_Hw), 1 = W branch (Ww,bw -> g_Ww).
// 256 threads = 8 warps; warp owns one output row m = r*192+d of the
// [12288 x 192] weight matrix. Coalesced lane-strided reads of the row,
// pools staged in shared (bank-conflict-free stride-32 access),
// 16-batch dot products reduced via shfl_xor.
__global__ void __launch_bounds__(256) rhw_weights_kernel(
        const float* __restrict__ Wh, const float* __restrict__ bh,
        const float* __restrict__ Wwp, const float* __restrict__ bw) {
    const int tid  = threadIdx.x;
    const int warp = tid >> 5;
    const int lane = tid & 31;
    const int m    = blockIdx.x * 8 + warp;   // 0..12287
    const int r    = m / H_;
    const int d    = m - r * H_;
    const int wbranch = blockIdx.y;

    __shared__ float sp[B_][H_];
    {
        const float* pool = wbranch ? g_wp : g_hp;
        for (int i = tid; i < B_ * H_; i += 256)
            sp[i / H_][i - (i / H_) * H_] = pool[i];
    }
    __syncthreads();

    const float* Wsrc = wbranch ? Wwp : Wh;
    const float* bsrc = wbranch ? bw  : bh;
    const float* wrow = Wsrc + (long)m * H_;

    float wv0 = wrow[lane +   0];
    float wv1 = wrow[lane +  32];
    float wv2 = wrow[lane +  64];
    float wv3 = wrow[lane +  96];
    float wv4 = wrow[lane + 128];
    float wv5 = wrow[lane + 160];

    float keep = 0.f;
    #pragma unroll
    for (int b = 0; b < B_; b++) {
        float s = wv0 * sp[b][lane +   0];
        s = fmaf(wv1, sp[b][lane +  32], s);
        s = fmaf(wv2, sp[b][lane +  64], s);
        s = fmaf(wv3, sp[b][lane +  96], s);
        s = fmaf(wv4, sp[b][lane + 128], s);
        s = fmaf(wv5, sp[b][lane + 160], s);
        #pragma unroll
        for (int off = 16; off >= 1; off >>= 1)
            s += __shfl_xor_sync(0xffffffffu, s, off);
        if (lane == b) keep = s;
    }

    if (lane < B_) {
        const float v = sigmoidf_(keep + bsrc[m]);
        if (wbranch == 0)
            g_Hw[(lane * H_ + d) * R_ + r] = v;      // [B][H][R]
        else
            g_Ww[(lane * R_ + r) * W_ + d] = v;      // [B][R][W]
    }
}

// ---------------- kernel 3c: T[b][r][c] = p[r]*sigmoid(Wc@cp+bc) ---------
// Warp-per-row (m = r*64+d), rows of 64: two coalesced loads per lane.
__global__ void __launch_bounds__(256) cw_kernel(
        const float* __restrict__ Wc, const float* __restrict__ bc,
        const float* __restrict__ p) {
    const int tid  = threadIdx.x;
    const int warp = tid >> 5;
    const int lane = tid & 31;
    const int m    = blockIdx.x * 8 + warp;   // 0..4095
    const int r    = m / C_;
    const int d    = m - r * C_;

    __shared__ float sp[B_][C_];
    for (int i = tid; i < B_ * C_; i += 256)
        sp[i >> 6][i & 63] = g_cp[i];
    __syncthreads();

    const float* wrow = Wc + m * C_;
    const float wv0 = wrow[lane];
    const float wv1 = wrow[lane + 32];

    float keep = 0.f;
    #pragma unroll
    for (int b = 0; b < B_; b++) {
        float s = fmaf(wv1, sp[b][lane + 32], wv0 * sp[b][lane]);
        #pragma unroll
        for (int off = 16; off >= 1; off >>= 1)
            s += __shfl_xor_sync(0xffffffffu, s, off);
        if (lane == b) keep = s;
    }
    if (lane < B_) {
        const float v = p[r] * sigmoidf_(keep + bc[m]);
        g_T[(lane * R_ + r) * C_ + d] = v;            // [B][R][C]
    }
}

// ---------------- kernel 4: main fused GEMM + elementwise ----------------
// Block = (h, w-half, b). Smem: M[r][c] = T[b][r][c]*Hw[b][h][r] (64x64),
// V[r][w'] = Ww[b][r][half*96 + w'] (64x96). Each of 192 threads owns an
// 8c x 4w register tile computed with packed f32x2 FMAs over r=0..63.
__global__ void __launch_bounds__(192) main_kernel(const float* __restrict__ X,
                                                   float* __restrict__ out) {
    const int h    = blockIdx.x;   // 0..191
    const int half = blockIdx.y;   // 0..1
    const int b    = blockIdx.z;   // 0..15

    const int tid = threadIdx.x;
    const int tc  = tid / 24;      // 0..7
    const int tw  = tid - tc * 24; // 0..23

    __shared__ float sM[R_ * C_];        // 16 KB  [r][c]
    __shared__ float sV[R_ * 96];        // 24 KB  [r][w']
    __shared__ float sh[R_];

    if (tid < R_) sh[tid] = g_Hw[(b * H_ + h) * R_ + tid];
    __syncthreads();

    // fill M = T * hw   (T layout [B][R][C], coalesced float4)
    {
        const float4* T4  = (const float4*)(g_T + b * (R_ * C_));
        float4*       sM4 = (float4*)sM;
        for (int i = tid; i < (R_ * C_) / 4; i += 192) {
            float4 t = T4[i];
            const float hv = sh[i >> 4];  // r = i / (C_/4)
            t.x *= hv; t.y *= hv; t.z *= hv; t.w *= hv;
            sM4[i] = t;
        }
    }
    // fill V half
    {
        float4* sV4 = (float4*)sV;
        for (int i = tid; i < R_ * 24; i += 192) {
            const int r = i / 24;
            const int j = i - r * 24;
            sV4[r * 24 + j] =
                ((const float4*)(g_Ww + (b * R_ + r) * W_ + half * 96))[j];
        }
    }
    __syncthreads();

    const float4* sM4 = (const float4*)sM;
    const float4* sV4 = (const float4*)sV;

    unsigned long long acc[4][4];  // [c-pair][w]
    #pragma unroll
    for (int i = 0; i < 4; i++)
        #pragma unroll
        for (int j = 0; j < 4; j++) acc[i][j] = 0ull;

    #pragma unroll 4
    for (int r = 0; r < R_; r++) {
        const float4 a0 = sM4[r * 16 + tc];       // c = 4tc .. 4tc+3
        const float4 a1 = sM4[r * 16 + 8 + tc];   // c = 32+4tc .. 32+4tc+3
        const float4 bv = sV4[r * 24 + tw];       // w = 4tw .. 4tw+3

        unsigned long long A0 = pk2(a0.x, a0.y);
        unsigned long long A1 = pk2(a0.z, a0.w);
        unsigned long long A2 = pk2(a1.x, a1.y);
        unsigned long long A3 = pk2(a1.z, a1.w);

        unsigned long long Bx = pk2(bv.x, bv.x);
        unsigned long long By = pk2(bv.y, bv.y);
        unsigned long long Bz = pk2(bv.z, bv.z);
        unsigned long long Bw = pk2(bv.w, bv.w);

        fma2(acc[0][0], A0, Bx); fma2(acc[0][1], A0, By);
        fma2(acc[0][2], A0, Bz); fma2(acc[0][3], A0, Bw);
        fma2(acc[1][0], A1, Bx); fma2(acc[1][1], A1, By);
        fma2(acc[1][2], A1, Bz); fma2(acc[1][3], A1, Bw);
        fma2(acc[2][0], A2, Bx); fma2(acc[2][1], A2, By);
        fma2(acc[2][2], A2, Bz); fma2(acc[2][3], A2, Bw);
        fma2(acc[3][0], A3, Bx); fma2(acc[3][1], A3, By);
        fma2(acc[3][2], A3, Bz); fma2(acc[3][3], A3, Bw);
    }

    // unpack: vals[ci][wj], ci: 0..3 -> c = 4tc+ci ; 4..7 -> c = 32+4tc+(ci-4)
    float vals[8][4];
    #pragma unroll
    for (int cp = 0; cp < 4; cp++) {
        #pragma unroll
        for (int wj = 0; wj < 4; wj++) {
            const float2 q = upk2(acc[cp][wj]);
            vals[2 * cp + 0][wj] = q.x;
            vals[2 * cp + 1][wj] = q.y;
        }
    }

    const int w0 = half * 96 + tw * 4;
    #pragma unroll
    for (int ci = 0; ci < 8; ci++) {
        const int c = (ci < 4) ? (tc * 4 + ci) : (32 + tc * 4 + (ci - 4));
        const int idx = ((b * C_ + c) * H_ + h) * W_ + w0;
        const float4 x = *(const float4*)(X + idx);
        float4 o;
        o.x = vals[ci][0] * x.x;
        o.y = vals[ci][1] * x.y;
        o.z = vals[ci][2] * x.z;
        o.w = vals[ci][3] * x.w;
        *(float4*)(out + idx) = o;
    }
}

// ---------------- launch ---------------------------------------------------
extern "C" void kernel_launch(void* const* d_in, const int* in_sizes, int n_in,
                              void* d_out, int out_size) {
    const float* X   = (const float*)d_in[0];
    const float* p   = (const float*)d_in[1];
    const float* Wc  = (const float*)d_in[2];
    const float* bc  = (const float*)d_in[3];
    const float* Wh  = (const float*)d_in[4];
    const float* bh  = (const float*)d_in[5];
    const float* Wwp = (const float*)d_in[6];
    const float* bw  = (const float*)d_in[7];
    float* out = (float*)d_out;

    pool_kernel<<<dim3(C_, B_), 192>>>(X);
    hw_pool_kernel<<<(B_ * H_ + 255) / 256, 256>>>();
    cw_kernel<<<(R_ * C_) / 8, 256>>>(Wc, bc, p);
    rhw_weights_kernel<<<dim3((R_ * H_) / 8, 2), 256>>>(Wh, bh, Wwp, bw);
    main_kernel<<<dim3(H_, 2, B_), 192>>>(X, out);
}